// round 10
// baseline (speedup 1.0000x reference)
#include <cuda_runtime.h>

// Problem constants (fixed by reference setup_inputs)
#define B_  4
#define C_  3
#define H_  384
#define W_  1248
#define W8_ (W_/8)                    // 156 chunks of 8 floats per row
#define H2_ (H_/2)                    // 192 y-pairs
#define PLANE_ (H_*W_)                // 479232
#define OUT_PER_SIDE_ ((long long)B_*9*C_*H_*W_)  // 51,757,056
#define T_PER_SIDE_ (B_*C_*H2_*W8_)               // 359,424 threads per side
#define NBLOCKS_ (2*T_PER_SIDE_/256)              // 2808 (exact)

// 256-bit streaming store (sm_100a+): one STG.256 -> warp writes 1KB contiguous.
__device__ __forceinline__ void stg256_cs(float* p, const float* w)
{
    asm volatile("st.global.cs.v8.f32 [%0], {%1,%2,%3,%4,%5,%6,%7,%8};"
                 :: "l"(p), "f"(w[0]), "f"(w[1]), "f"(w[2]), "f"(w[3]),
                    "f"(w[4]), "f"(w[5]), "f"(w[6]), "f"(w[7])
                 : "memory");
}

// out[b, (dy*3+dx)*C + c, y, x] = in[b, c, y+dy-1, x+dx-1]  (0 when OOB)
// Each thread produces an 8-wide x-chunk for TWO consecutive rows (2yp, 2yp+1),
// all 9 (dy,dx) planes: 18 STG.256 from a 4x10 register window.
// Lane stride = 32B = store width -> warp bursts stay fully contiguous.
// Last block writes the 81-element one-hot filter (eye(9) -> idx%10==0).
__global__ void __launch_bounds__(256) unfold_kernel(
    const float* __restrict__ left,
    const float* __restrict__ right,
    float* __restrict__ out)
{
    if (blockIdx.x == NBLOCKS_) {
        int i = threadIdx.x;
        if (i < 81) out[2 * OUT_PER_SIDE_ + i] = (i % 10 == 0) ? 1.0f : 0.0f;
        return;
    }

    int t = blockIdx.x * 256 + threadIdx.x;   // exact fit: NBLOCKS_*256 == 2*T_PER_SIDE_

    const float* in = left;
    float* o = out;
    if (t >= T_PER_SIDE_) { t -= T_PER_SIDE_; in = right; o = out + OUT_PER_SIDE_; }

    int chunk = t % W8_;
    int rem   = t / W8_;
    int yp    = rem % H2_;            // y-pair index: rows 2yp, 2yp+1
    rem      /= H2_;
    int c     = rem % C_;
    int b     = rem / C_;
    int x     = chunk * 8;
    int y0    = 2 * yp;

    const float* base = in + ((b * C_ + c) * H_) * (long long)W_;

    // v[j][0..9] = input[y0-1+j][x-1 .. x+8], j=0..3, with zero padding
    float v[4][10];
#pragma unroll
    for (int j = 0; j < 4; j++) {
        int yy = y0 - 1 + j;
        if (yy < 0 || yy >= H_) {
#pragma unroll
            for (int i = 0; i < 10; i++) v[j][i] = 0.f;
        } else {
            const float* row = base + yy * W_ + x;
            float4 a = *(const float4*)row;            // 32B-aligned
            float4 d = *(const float4*)(row + 4);
            v[j][1] = a.x; v[j][2] = a.y; v[j][3] = a.z; v[j][4] = a.w;
            v[j][5] = d.x; v[j][6] = d.y; v[j][7] = d.z; v[j][8] = d.w;
            v[j][0] = (x > 0)       ? __ldg(row - 1) : 0.f;
            v[j][9] = (x + 8 < W_)  ? __ldg(row + 8) : 0.f;
        }
    }

    // Output base for k=0 (channel index k*C + c), row y0
    float* ob = o + ((((long long)b * 9 * C_ + c) * H_ + y0) * W_ + x);

#pragma unroll
    for (int dy = 0; dy < 3; dy++) {
#pragma unroll
        for (int dx = 0; dx < 3; dx++) {
            float* p = ob + (long long)(dy * 3 + dx) * (C_ * PLANE_);
            // row y0 uses v[dy], row y0+1 uses v[dy+1]
            stg256_cs(p,      &v[dy][dx]);
            stg256_cs(p + W_, &v[dy + 1][dx]);
        }
    }
}

extern "C" void kernel_launch(void* const* d_in, const int* in_sizes, int n_in,
                              void* d_out, int out_size)
{
    const float* left  = (const float*)d_in[0];
    const float* right = (const float*)d_in[1];
    float* out = (float*)d_out;

    unfold_kernel<<<NBLOCKS_ + 1, 256>>>(left, right, out);
}